// round 3
// baseline (speedup 1.0000x reference)
#include <cuda_runtime.h>
#include <math_constants.h>

#define BT 16
#define VH 6890
#define VO 2048
#define NH (BT*VH)          /* 110240 */
#define NO (BT*VO)          /* 32768  */
#define TPB 128
#define RPT2 7              /* packed row-pairs per thread -> 14 rows */
#define RPB (TPB*RPT2*2)    /* rows per block = 1792 */
#define RCHUNKS 4           /* 4*1792 = 7168 >= 6890 */
#define JT 256
#define JCHUNKS (VO/JT)     /* 8 */

// Scratch (static __device__ — no allocations allowed)
__device__ float4   g_objP[2*NO];   // per object: (-2x,-2y,-2z, x^2+y^2+z^2)
__device__ unsigned g_dh[2*NH];     // min d^2 bits, human rows  [ds][b][i]
__device__ unsigned g_do[2*NO];     // min d^2 bits, object cols [ds][b][j]
__device__ double   g_acc[8];       // [dir(h/o)][P, Spos, Sneg, Shub]
__device__ unsigned g_done;

// ---- packed f32x2 helpers (Blackwell FFMA2 path) ----
union F2U { float2 f; unsigned long long u; };

__device__ __forceinline__ float2 fma2(float2 a, float2 b, float2 c) {
    F2U A, B, C, D; A.f = a; B.f = b; C.f = c;
    asm("fma.rn.f32x2 %0, %1, %2, %3;" : "=l"(D.u) : "l"(A.u), "l"(B.u), "l"(C.u));
    return D.f;
}
__device__ __forceinline__ float2 add2(float2 a, float2 b) {
    F2U A, B, D; A.f = a; B.f = b;
    asm("add.rn.f32x2 %0, %1, %2;" : "=l"(D.u) : "l"(A.u), "l"(B.u));
    return D.f;
}

// fused init + object preprocessing
__global__ void k_initprep(const float* __restrict__ o, const float* __restrict__ go) {
    int i = blockIdx.x * blockDim.x + threadIdx.x;
    if (i < 2*NH) g_dh[i] = 0x7F800000u;  // +inf
    if (i < 8)    g_acc[i] = 0.0;
    if (i == 8)   g_done = 0u;
    if (i < 2*NO) {
        g_do[i] = 0x7F800000u;
        int ds = i >> 15;            // NO == 1<<15
        int r  = i & (NO - 1);
        const float* p = (ds ? go : o) + r * 3;
        float x = p[0], y = p[1], z = p[2];
        g_objP[i] = make_float4(-2.f*x, -2.f*y, -2.f*z,
                                fmaf(x, x, fmaf(y, y, z*z)));
    }
}

__global__ void __launch_bounds__(TPB) k_pair(const float* __restrict__ h,
                                              const float* __restrict__ gh) {
    __shared__ float2   sOx[JT], sOy[JT], sOz[JT], sOw[JT];  // duplicated halves
    __shared__ unsigned sCol[JT];
    const int ds = blockIdx.z, b = blockIdx.y;
    const int rc = blockIdx.x / JCHUNKS, jc = blockIdx.x % JCHUNKS;
    const int t  = threadIdx.x;
    const int objOff = ds*NO + b*VO + jc*JT;

    // stage objects into smem, coordinate duplicated into both f32x2 halves
#pragma unroll
    for (int s = t; s < JT; s += TPB) {
        float4 a = g_objP[objOff + s];
        sOx[s] = make_float2(a.x, a.x);
        sOy[s] = make_float2(a.y, a.y);
        sOz[s] = make_float2(a.z, a.z);
        sOw[s] = make_float2(a.w, a.w);
        sCol[s] = 0x7F800000u;
    }

    const float* H = (ds ? gh : h) + (size_t)b * VH * 3;
    // two adjacent human rows packed per f32x2 register pair
    float2 hx2[RPT2], hy2[RPT2], hz2[RPT2], hh2[RPT2], rmin2[RPT2];
    const int rowBase = rc * RPB + 2 * t;
#pragma unroll
    for (int k = 0; k < RPT2; k++) {
        int rowA = rowBase + k * (2*TPB);
        int rowB = rowA + 1;
        float xA=0.f,yA=0.f,zA=0.f,sA=CUDART_INF_F;
        float xB=0.f,yB=0.f,zB=0.f,sB=CUDART_INF_F;
        if (rowA < VH) {
            xA = H[rowA*3+0]; yA = H[rowA*3+1]; zA = H[rowA*3+2];
            sA = fmaf(xA, xA, fmaf(yA, yA, zA*zA));
        }
        if (rowB < VH) {
            xB = H[rowB*3+0]; yB = H[rowB*3+1]; zB = H[rowB*3+2];
            sB = fmaf(xB, xB, fmaf(yB, yB, zB*zB));
        }
        hx2[k] = make_float2(xA, xB);
        hy2[k] = make_float2(yA, yB);
        hz2[k] = make_float2(zA, zB);
        hh2[k] = make_float2(sA, sB);   // +inf halves never win col-min
        rmin2[k] = make_float2(CUDART_INF_F, CUDART_INF_F);
    }
    __syncthreads();

#pragma unroll 2
    for (int j = 0; j < JT; j++) {
        float2 ox = sOx[j], oy = sOy[j], oz = sOz[j], ow = sOw[j];
        float2 cm2 = make_float2(CUDART_INF_F, CUDART_INF_F);
#pragma unroll
        for (int k = 0; k < RPT2; k++) {
            float2 q2 = fma2(hz2[k], oz, ow);     // oo - 2 h·o (two rows)
            q2 = fma2(hy2[k], oy, q2);
            q2 = fma2(hx2[k], ox, q2);
            rmin2[k].x = fminf(rmin2[k].x, q2.x); // row-min in q-space (hh later)
            rmin2[k].y = fminf(rmin2[k].y, q2.y);
            float2 c2 = add2(q2, hh2[k]);         // full d^2 for col-min
            cm2.x = fminf(cm2.x, c2.x);
            cm2.y = fminf(cm2.y, c2.y);
        }
        float cm = fminf(cm2.x, cm2.y);
        unsigned u = __float_as_uint(fmaxf(cm, 0.f)); // >=0 -> uint order == float order
        u = __reduce_min_sync(0xFFFFFFFFu, u);
        if ((t & 31) == 0) atomicMin(&sCol[j], u);
    }
    __syncthreads();

#pragma unroll
    for (int s = t; s < JT; s += TPB)
        atomicMin(&g_do[objOff + s], sCol[s]);
#pragma unroll
    for (int k = 0; k < RPT2; k++) {
        int rowA = rowBase + k * (2*TPB);
        int rowB = rowA + 1;
        if (rowA < VH) {
            float d2 = fmaxf(rmin2[k].x + hh2[k].x, 0.f);
            atomicMin(&g_dh[ds*NH + b*VH + rowA], __float_as_uint(d2));
        }
        if (rowB < VH) {
            float d2 = fmaxf(rmin2[k].y + hh2[k].y, 0.f);
            atomicMin(&g_dh[ds*NH + b*VH + rowB], __float_as_uint(d2));
        }
    }
}

#define LOSS_BLOCKS 64

__global__ void k_loss(float* out) {
    const int dir = blockIdx.y;          // 0 = human rows, 1 = object cols
    const int N   = dir ? NO : NH;
    float P = 0.f, Spos = 0.f, Sneg = 0.f, Shub = 0.f;
    for (int i = blockIdx.x * blockDim.x + threadIdx.x; i < N; i += LOSS_BLOCKS * blockDim.x) {
        unsigned pb = dir ? g_do[i]      : g_dh[i];
        unsigned gb = dir ? g_do[NO + i] : g_dh[NH + i];
        float pd = sqrtf(__uint_as_float(pb));
        float gd = sqrtf(__uint_as_float(gb));
        bool tpos = gd < 0.2f;
        float z = (0.2f - pd) * 100.f;
        float p = 1.f / (1.f + expf(-z));
        p = fminf(fmaxf(p, 1e-6f), 1.f - 1e-6f);
        float l = tpos ? -logf(p) : -logf(1.f - p);
        if (tpos) { P += 1.f; Spos += l; } else { Sneg += l; }
        float over = fmaxf(pd - 0.1f, 0.f);
        float hub  = (over < 0.01f) ? (50.f * over * over) : (over - 0.005f);
        if (tpos) Shub += hub;
    }
#pragma unroll
    for (int off = 16; off; off >>= 1) {
        P    += __shfl_down_sync(0xFFFFFFFFu, P,    off);
        Spos += __shfl_down_sync(0xFFFFFFFFu, Spos, off);
        Sneg += __shfl_down_sync(0xFFFFFFFFu, Sneg, off);
        Shub += __shfl_down_sync(0xFFFFFFFFu, Shub, off);
    }
    __shared__ float s[4][8];
    int w = threadIdx.x >> 5, l = threadIdx.x & 31;
    if (l == 0) { s[0][w] = P; s[1][w] = Spos; s[2][w] = Sneg; s[3][w] = Shub; }
    __syncthreads();
    if (threadIdx.x == 0) {
        float a0 = 0, a1 = 0, a2 = 0, a3 = 0;
        int nw = (blockDim.x + 31) >> 5;
        for (int k = 0; k < nw; k++) { a0 += s[0][k]; a1 += s[1][k]; a2 += s[2][k]; a3 += s[3][k]; }
        atomicAdd(&g_acc[dir*4 + 0], (double)a0);
        atomicAdd(&g_acc[dir*4 + 1], (double)a1);
        atomicAdd(&g_acc[dir*4 + 2], (double)a2);
        atomicAdd(&g_acc[dir*4 + 3], (double)a3);
        __threadfence();
        unsigned v = atomicAdd(&g_done, 1u);
        if (v == 2*LOSS_BLOCKS - 1) {    // last block: finalize
            double Ph = g_acc[0], Sph = g_acc[1], Snh = g_acc[2], Shh = g_acc[3];
            double Po = g_acc[4], Spo = g_acc[5], Sno = g_acc[6], Sho = g_acc[7];
            double negh = (double)NH - Ph, nego = (double)NO - Po;
            double pwh = (negh + 1e-6) / (Ph + 1e-6);
            double pwo = (nego + 1e-6) / (Po + 1e-6);
            double bh = (pwh * Sph + Snh) / (double)NH;
            double bo = (pwo * Spo + Sno) / (double)NO;
            double Lbce = 0.5 * (bh + bo);
            double LhH = (Ph > 0.0) ? (Shh / fmax(Ph, 1.0)) : 0.0;
            double LhO = (Po > 0.0) ? (Sho / fmax(Po, 1.0)) : 0.0;
            out[0] = (float)(0.5 * Lbce + (LhH + LhO));
        }
    }
}

extern "C" void kernel_launch(void* const* d_in, const int* in_sizes, int n_in,
                              void* d_out, int out_size) {
    const float* h  = (const float*)d_in[0];
    const float* o  = (const float*)d_in[1];
    const float* gh = (const float*)d_in[2];
    const float* go = (const float*)d_in[3];

    k_initprep<<<(2*NH + 255)/256, 256>>>(o, go);
    dim3 gp(RCHUNKS * JCHUNKS, BT, 2);      // 32 x 16 x 2 = 1024 blocks
    k_pair<<<gp, TPB>>>(h, gh);
    dim3 gl(LOSS_BLOCKS, 2);
    k_loss<<<gl, 256>>>((float*)d_out);
}

// round 4
// speedup vs baseline: 1.0846x; 1.0846x over previous
#include <cuda_runtime.h>
#include <math_constants.h>

#define BT 16
#define VH 6890
#define VO 2048
#define NH (BT*VH)          /* 110240 */
#define NO (BT*VO)          /* 32768  */
#define TPB 256
#define RPT 4
#define ROWCHUNK (TPB*RPT)  /* 1024 */
#define RCHUNKS ((VH+ROWCHUNK-1)/ROWCHUNK)  /* 7 */
#define JT 256
#define J2 (JT/2)           /* 128 packed object-pairs */
#define JCHUNKS (VO/JT)     /* 8 */

// Scratch (static __device__ — no allocations allowed)
__device__ float4   g_objP[2*NO];   // per object: (-2x,-2y,-2z, x^2+y^2+z^2)
__device__ unsigned g_dh[2*NH];     // min d^2 bits, human rows  [ds][b][i]
__device__ unsigned g_do[2*NO];     // min d^2 bits, object cols [ds][b][j]
__device__ double   g_acc[8];       // [dir(h/o)][P, Spos, Sneg, Shub]
__device__ unsigned g_done;

// ---- packed f32x2 helpers (Blackwell FFMA2 path) ----
union F2U { float2 f; unsigned long long u; };

__device__ __forceinline__ float2 fma2(float2 a, float2 b, float2 c) {
    F2U A, B, C, D; A.f = a; B.f = b; C.f = c;
    asm("fma.rn.f32x2 %0, %1, %2, %3;" : "=l"(D.u) : "l"(A.u), "l"(B.u), "l"(C.u));
    return D.f;
}
__device__ __forceinline__ float2 add2(float2 a, float2 b) {
    F2U A, B, D; A.f = a; B.f = b;
    asm("add.rn.f32x2 %0, %1, %2;" : "=l"(D.u) : "l"(A.u), "l"(B.u));
    return D.f;
}

// fused init + object preprocessing
__global__ void k_initprep(const float* __restrict__ o, const float* __restrict__ go) {
    int i = blockIdx.x * blockDim.x + threadIdx.x;
    if (i < 2*NH) g_dh[i] = 0x7F800000u;  // +inf
    if (i < 8)    g_acc[i] = 0.0;
    if (i == 8)   g_done = 0u;
    if (i < 2*NO) {
        g_do[i] = 0x7F800000u;
        int ds = i >> 15;            // NO == 1<<15
        int r  = i & (NO - 1);
        const float* p = (ds ? go : o) + r * 3;
        float x = p[0], y = p[1], z = p[2];
        g_objP[i] = make_float4(-2.f*x, -2.f*y, -2.f*z,
                                fmaf(x, x, fmaf(y, y, z*z)));
    }
}

__global__ void __launch_bounds__(TPB) k_pair(const float* __restrict__ h,
                                              const float* __restrict__ gh) {
    __shared__ float2   sOx[J2], sOy[J2], sOz[J2], sOw[J2];
    __shared__ unsigned sCol[JT];
    const int ds = blockIdx.z, b = blockIdx.y;
    const int rc = blockIdx.x / JCHUNKS, jc = blockIdx.x % JCHUNKS;
    const int t  = threadIdx.x;
    const int objOff = ds*NO + b*VO + jc*JT;

    // stage objects packed SoA: half the threads pack two objects each
    if (t < J2) {
        float4 a = g_objP[objOff + 2*t];
        float4 c = g_objP[objOff + 2*t + 1];
        sOx[t] = make_float2(a.x, c.x);
        sOy[t] = make_float2(a.y, c.y);
        sOz[t] = make_float2(a.z, c.z);
        sOw[t] = make_float2(a.w, c.w);
    }
    sCol[t] = 0x7F800000u;

    const float* H = (ds ? gh : h) + (size_t)b * VH * 3;
    float hx[RPT], hy[RPT], hz[RPT];
    float2 hh2[RPT];
    float rA[RPT], rB[RPT];   // per-half row-min accumulators (q-space)
    const int row0 = rc * ROWCHUNK + t;
#pragma unroll
    for (int k = 0; k < RPT; k++) {
        int row = row0 + k * TPB;
        float x = 0.f, y = 0.f, z = 0.f, s = CUDART_INF_F;
        if (row < VH) {
            x = H[row*3+0]; y = H[row*3+1]; z = H[row*3+2];
            s = fmaf(x, x, fmaf(y, y, z*z));
        }
        hx[k] = x; hy[k] = y; hz[k] = z;
        hh2[k] = make_float2(s, s);   // +inf for invalid rows -> never wins col-min
        rA[k] = CUDART_INF_F; rB[k] = CUDART_INF_F;
    }
    __syncthreads();

#define UNR 4
#pragma unroll 1
    for (int j0 = 0; j0 < J2; j0 += UNR) {
        // batch all smem operand loads up front (hide LDS latency, enable .reuse)
        float2 ox[UNR], oy[UNR], oz[UNR], ow[UNR];
#pragma unroll
        for (int u = 0; u < UNR; u++) {
            ox[u] = sOx[j0+u]; oy[u] = sOy[j0+u];
            oz[u] = sOz[j0+u]; ow[u] = sOw[j0+u];
        }
#pragma unroll
        for (int u = 0; u < UNR; u++) {
            float cmA = CUDART_INF_F, cmB = CUDART_INF_F;
#pragma unroll
            for (int k = 0; k < RPT; k++) {
                float2 hz2 = make_float2(hz[k], hz[k]);
                float2 hy2 = make_float2(hy[k], hy[k]);
                float2 hx2 = make_float2(hx[k], hx[k]);
                float2 q2 = fma2(hz2, oz[u], ow[u]);   // oo - 2 h·o (two objects)
                q2 = fma2(hy2, oy[u], q2);
                q2 = fma2(hx2, ox[u], q2);
                rA[k] = fminf(rA[k], q2.x);            // row-min in q-space
                rB[k] = fminf(rB[k], q2.y);
                float2 c2 = add2(q2, hh2[k]);          // full d^2 for col-min
                cmA = fminf(cmA, c2.x);
                cmB = fminf(cmB, c2.y);
            }
            unsigned uA = __float_as_uint(fmaxf(cmA, 0.f));  // >=0: uint order == float order
            unsigned uB = __float_as_uint(fmaxf(cmB, 0.f));
            uA = __reduce_min_sync(0xFFFFFFFFu, uA);
            uB = __reduce_min_sync(0xFFFFFFFFu, uB);
            if ((t & 31) == 0) {
                atomicMin(&sCol[2*(j0+u)],     uA);
                atomicMin(&sCol[2*(j0+u) + 1], uB);
            }
        }
    }
    __syncthreads();

    atomicMin(&g_do[objOff + t], sCol[t]);
#pragma unroll
    for (int k = 0; k < RPT; k++) {
        int row = row0 + k * TPB;
        if (row < VH) {
            float d2 = fmaxf(fminf(rA[k], rB[k]) + hh2[k].x, 0.f);
            atomicMin(&g_dh[ds*NH + b*VH + row], __float_as_uint(d2));
        }
    }
}

#define LOSS_BLOCKS 64

__global__ void k_loss(float* out) {
    const int dir = blockIdx.y;          // 0 = human rows, 1 = object cols
    const int N   = dir ? NO : NH;
    float P = 0.f, Spos = 0.f, Sneg = 0.f, Shub = 0.f;
    for (int i = blockIdx.x * blockDim.x + threadIdx.x; i < N; i += LOSS_BLOCKS * blockDim.x) {
        unsigned pb = dir ? g_do[i]      : g_dh[i];
        unsigned gb = dir ? g_do[NO + i] : g_dh[NH + i];
        float pd = sqrtf(__uint_as_float(pb));
        float gd = sqrtf(__uint_as_float(gb));
        bool tpos = gd < 0.2f;
        float z = (0.2f - pd) * 100.f;
        float p = 1.f / (1.f + expf(-z));
        p = fminf(fmaxf(p, 1e-6f), 1.f - 1e-6f);
        float l = tpos ? -logf(p) : -logf(1.f - p);
        if (tpos) { P += 1.f; Spos += l; } else { Sneg += l; }
        float over = fmaxf(pd - 0.1f, 0.f);
        float hub  = (over < 0.01f) ? (50.f * over * over) : (over - 0.005f);
        if (tpos) Shub += hub;
    }
#pragma unroll
    for (int off = 16; off; off >>= 1) {
        P    += __shfl_down_sync(0xFFFFFFFFu, P,    off);
        Spos += __shfl_down_sync(0xFFFFFFFFu, Spos, off);
        Sneg += __shfl_down_sync(0xFFFFFFFFu, Sneg, off);
        Shub += __shfl_down_sync(0xFFFFFFFFu, Shub, off);
    }
    __shared__ float s[4][8];
    int w = threadIdx.x >> 5, l = threadIdx.x & 31;
    if (l == 0) { s[0][w] = P; s[1][w] = Spos; s[2][w] = Sneg; s[3][w] = Shub; }
    __syncthreads();
    if (threadIdx.x == 0) {
        float a0 = 0, a1 = 0, a2 = 0, a3 = 0;
        int nw = (blockDim.x + 31) >> 5;
        for (int k = 0; k < nw; k++) { a0 += s[0][k]; a1 += s[1][k]; a2 += s[2][k]; a3 += s[3][k]; }
        atomicAdd(&g_acc[dir*4 + 0], (double)a0);
        atomicAdd(&g_acc[dir*4 + 1], (double)a1);
        atomicAdd(&g_acc[dir*4 + 2], (double)a2);
        atomicAdd(&g_acc[dir*4 + 3], (double)a3);
        __threadfence();
        unsigned v = atomicAdd(&g_done, 1u);
        if (v == 2*LOSS_BLOCKS - 1) {    // last block: finalize
            double Ph = g_acc[0], Sph = g_acc[1], Snh = g_acc[2], Shh = g_acc[3];
            double Po = g_acc[4], Spo = g_acc[5], Sno = g_acc[6], Sho = g_acc[7];
            double negh = (double)NH - Ph, nego = (double)NO - Po;
            double pwh = (negh + 1e-6) / (Ph + 1e-6);
            double pwo = (nego + 1e-6) / (Po + 1e-6);
            double bh = (pwh * Sph + Snh) / (double)NH;
            double bo = (pwo * Spo + Sno) / (double)NO;
            double Lbce = 0.5 * (bh + bo);
            double LhH = (Ph > 0.0) ? (Shh / fmax(Ph, 1.0)) : 0.0;
            double LhO = (Po > 0.0) ? (Sho / fmax(Po, 1.0)) : 0.0;
            out[0] = (float)(0.5 * Lbce + (LhH + LhO));
        }
    }
}

extern "C" void kernel_launch(void* const* d_in, const int* in_sizes, int n_in,
                              void* d_out, int out_size) {
    const float* h  = (const float*)d_in[0];
    const float* o  = (const float*)d_in[1];
    const float* gh = (const float*)d_in[2];
    const float* go = (const float*)d_in[3];

    k_initprep<<<(2*NH + 255)/256, 256>>>(o, go);
    dim3 gp(RCHUNKS * JCHUNKS, BT, 2);      // 56 x 16 x 2 = 1792 blocks
    k_pair<<<gp, TPB>>>(h, gh);
    dim3 gl(LOSS_BLOCKS, 2);
    k_loss<<<gl, 256>>>((float*)d_out);
}

// round 6
// speedup vs baseline: 1.1502x; 1.0605x over previous
#include <cuda_runtime.h>
#include <math_constants.h>

#define BT 16
#define VH 6890
#define VO 2048
#define NH (BT*VH)          /* 110240 */
#define NO (BT*VO)          /* 32768  */
#define TPB 256
#define RPT 4
#define ROWCHUNK (TPB*RPT)  /* 1024 */
#define RCHUNKS ((VH+ROWCHUNK-1)/ROWCHUNK)  /* 7 */
#define JT 256
#define J2 (JT/2)           /* 128 packed object-pairs */
#define JCHUNKS (VO/JT)     /* 8 */

// Scratch (static __device__ — no allocations allowed)
__device__ float4   g_objP[2*NO];   // per object: (-2x,-2y,-2z, x^2+y^2+z^2)
__device__ unsigned g_dh[2*NH];     // min d^2 bits, human rows  [ds][b][i]
__device__ unsigned g_do[2*NO];     // min d^2 bits, object cols [ds][b][j]
__device__ double   g_acc[8];       // [dir(h/o)][P, Spos, Sneg, Shub]
__device__ unsigned g_done;

// ---- packed f32x2 helpers (Blackwell FFMA2 path) ----
union F2U { float2 f; unsigned long long u; };

__device__ __forceinline__ float2 fma2(float2 a, float2 b, float2 c) {
    F2U A, B, C, D; A.f = a; B.f = b; C.f = c;
    asm("fma.rn.f32x2 %0, %1, %2, %3;" : "=l"(D.u) : "l"(A.u), "l"(B.u), "l"(C.u));
    return D.f;
}
__device__ __forceinline__ float2 add2(float2 a, float2 b) {
    F2U A, B, D; A.f = a; B.f = b;
    asm("add.rn.f32x2 %0, %1, %2;" : "=l"(D.u) : "l"(A.u), "l"(B.u));
    return D.f;
}

// fused init + object preprocessing (vectorized g_dh fill)
// grid MUST cover 2*NO = 65536 threads (g_do/g_objP); uint4 fill guard is internal.
__global__ void k_initprep(const float* __restrict__ o, const float* __restrict__ go) {
    int i = blockIdx.x * blockDim.x + threadIdx.x;
    const unsigned INF = 0x7F800000u;
    if (i < (2*NH)/4) {   // 55120 uint4 stores cover 220480 entries exactly
        ((uint4*)g_dh)[i] = make_uint4(INF, INF, INF, INF);
    }
    if (i < 8)  g_acc[i] = 0.0;
    if (i == 8) g_done = 0u;
    if (i < 2*NO) {
        g_do[i] = INF;
        int ds = i >> 15;            // NO == 1<<15
        int r  = i & (NO - 1);
        const float* p = (ds ? go : o) + r * 3;
        float x = p[0], y = p[1], z = p[2];
        g_objP[i] = make_float4(-2.f*x, -2.f*y, -2.f*z,
                                fmaf(x, x, fmaf(y, y, z*z)));
    }
}

__global__ void __launch_bounds__(TPB) k_pair(const float* __restrict__ h,
                                              const float* __restrict__ gh) {
    __shared__ float4   sP[J2];   // {ox.x, ox.y, oy.x, oy.y} (two objects packed)
    __shared__ float4   sQ[J2];   // {oz.x, oz.y, ow.x, ow.y}
    __shared__ unsigned sCol[JT];
    const int ds = blockIdx.z, b = blockIdx.y;
    const int rc = blockIdx.x / JCHUNKS, jc = blockIdx.x % JCHUNKS;
    const int t  = threadIdx.x;
    const int objOff = ds*NO + b*VO + jc*JT;

    // stage objects packed SoA: half the threads pack two objects each
    if (t < J2) {
        float4 a = g_objP[objOff + 2*t];
        float4 c = g_objP[objOff + 2*t + 1];
        sP[t] = make_float4(a.x, c.x, a.y, c.y);
        sQ[t] = make_float4(a.z, c.z, a.w, c.w);
    }
    sCol[t] = 0x7F800000u;

    const float* H = (ds ? gh : h) + (size_t)b * VH * 3;
    float2 hx2[RPT], hy2[RPT], hz2[RPT], hh2[RPT];
    float rA[RPT], rB[RPT];   // per-half row-min accumulators (q-space)
    const int row0 = rc * ROWCHUNK + t;
#pragma unroll
    for (int k = 0; k < RPT; k++) {
        int row = row0 + k * TPB;
        float x = 0.f, y = 0.f, z = 0.f, s = CUDART_INF_F;
        if (row < VH) {
            x = H[row*3+0]; y = H[row*3+1]; z = H[row*3+2];
            s = fmaf(x, x, fmaf(y, y, z*z));
        }
        hx2[k] = make_float2(x, x);
        hy2[k] = make_float2(y, y);
        hz2[k] = make_float2(z, z);
        hh2[k] = make_float2(s, s);   // +inf for invalid rows -> never wins col-min
        rA[k] = CUDART_INF_F; rB[k] = CUDART_INF_F;
    }
    __syncthreads();

#define UNR 4
#pragma unroll 1
    for (int j0 = 0; j0 < J2; j0 += UNR) {
        // batch smem loads: 2 LDS.128 per j2 (operand pairs usable directly as f32x2)
        float4 vP[UNR], vQ[UNR];
#pragma unroll
        for (int u = 0; u < UNR; u++) { vP[u] = sP[j0+u]; vQ[u] = sQ[j0+u]; }
#pragma unroll
        for (int u = 0; u < UNR; u++) {
            float2 ox = make_float2(vP[u].x, vP[u].y);
            float2 oy = make_float2(vP[u].z, vP[u].w);
            float2 oz = make_float2(vQ[u].x, vQ[u].y);
            float2 ow = make_float2(vQ[u].z, vQ[u].w);
            float cmA = CUDART_INF_F, cmB = CUDART_INF_F;
#pragma unroll
            for (int k = 0; k < RPT; k++) {
                float2 q2 = fma2(hz2[k], oz, ow);   // oo - 2 h·o (two objects)
                q2 = fma2(hy2[k], oy, q2);
                q2 = fma2(hx2[k], ox, q2);
                rA[k] = fminf(rA[k], q2.x);         // row-min in q-space
                rB[k] = fminf(rB[k], q2.y);
                float2 c2 = add2(q2, hh2[k]);       // full d^2 for col-min
                cmA = fminf(cmA, c2.x);
                cmB = fminf(cmB, c2.y);
            }
            // no clamp: negative-d2 bit patterns (sign bit set) lose the unsigned
            // min to any positive candidate; k_loss clamps before sqrt.
            unsigned uA = __reduce_min_sync(0xFFFFFFFFu, __float_as_uint(cmA));
            unsigned uB = __reduce_min_sync(0xFFFFFFFFu, __float_as_uint(cmB));
            if ((t & 31) == 0) {
                atomicMin(&sCol[2*(j0+u)],     uA);
                atomicMin(&sCol[2*(j0+u) + 1], uB);
            }
        }
    }
    __syncthreads();

    atomicMin(&g_do[objOff + t], sCol[t]);
#pragma unroll
    for (int k = 0; k < RPT; k++) {
        int row = row0 + k * TPB;
        if (row < VH) {
            float d2 = fmaxf(fminf(rA[k], rB[k]) + hh2[k].x, 0.f);
            atomicMin(&g_dh[ds*NH + b*VH + row], __float_as_uint(d2));
        }
    }
}

#define LOSS_BLOCKS 64

__global__ void k_loss(float* out) {
    const int dir = blockIdx.y;          // 0 = human rows, 1 = object cols
    const int N   = dir ? NO : NH;
    float P = 0.f, Spos = 0.f, Sneg = 0.f, Shub = 0.f;
    for (int i = blockIdx.x * blockDim.x + threadIdx.x; i < N; i += LOSS_BLOCKS * blockDim.x) {
        unsigned pb = dir ? g_do[i]      : g_dh[i];
        unsigned gb = dir ? g_do[NO + i] : g_dh[NH + i];
        float pd = sqrtf(fmaxf(__uint_as_float(pb), 0.f));
        float gd = sqrtf(fmaxf(__uint_as_float(gb), 0.f));
        bool tpos = gd < 0.2f;
        float z = (0.2f - pd) * 100.f;
        // -log(clip(sigmoid(z))) == clamp(log1p(exp(-z)), 1e-6, -log(1e-6)); sym. for 1-p
        float w = tpos ? -z : z;
        float l = log1pf(expf(w));
        l = fminf(fmaxf(l, 1e-6f), 13.8155106f);
        if (tpos) { P += 1.f; Spos += l; } else { Sneg += l; }
        float over = fmaxf(pd - 0.1f, 0.f);
        float hub  = (over < 0.01f) ? (50.f * over * over) : (over - 0.005f);
        if (tpos) Shub += hub;
    }
#pragma unroll
    for (int off = 16; off; off >>= 1) {
        P    += __shfl_down_sync(0xFFFFFFFFu, P,    off);
        Spos += __shfl_down_sync(0xFFFFFFFFu, Spos, off);
        Sneg += __shfl_down_sync(0xFFFFFFFFu, Sneg, off);
        Shub += __shfl_down_sync(0xFFFFFFFFu, Shub, off);
    }
    __shared__ float s[4][8];
    int w = threadIdx.x >> 5, l = threadIdx.x & 31;
    if (l == 0) { s[0][w] = P; s[1][w] = Spos; s[2][w] = Sneg; s[3][w] = Shub; }
    __syncthreads();
    if (threadIdx.x == 0) {
        float a0 = 0, a1 = 0, a2 = 0, a3 = 0;
        int nw = (blockDim.x + 31) >> 5;
        for (int k = 0; k < nw; k++) { a0 += s[0][k]; a1 += s[1][k]; a2 += s[2][k]; a3 += s[3][k]; }
        atomicAdd(&g_acc[dir*4 + 0], (double)a0);
        atomicAdd(&g_acc[dir*4 + 1], (double)a1);
        atomicAdd(&g_acc[dir*4 + 2], (double)a2);
        atomicAdd(&g_acc[dir*4 + 3], (double)a3);
        __threadfence();
        unsigned v = atomicAdd(&g_done, 1u);
        if (v == 2*LOSS_BLOCKS - 1) {    // last block: finalize
            double Ph = g_acc[0], Sph = g_acc[1], Snh = g_acc[2], Shh = g_acc[3];
            double Po = g_acc[4], Spo = g_acc[5], Sno = g_acc[6], Sho = g_acc[7];
            double negh = (double)NH - Ph, nego = (double)NO - Po;
            double pwh = (negh + 1e-6) / (Ph + 1e-6);
            double pwo = (nego + 1e-6) / (Po + 1e-6);
            double bh = (pwh * Sph + Snh) / (double)NH;
            double bo = (pwo * Spo + Sno) / (double)NO;
            double Lbce = 0.5 * (bh + bo);
            double LhH = (Ph > 0.0) ? (Shh / fmax(Ph, 1.0)) : 0.0;
            double LhO = (Po > 0.0) ? (Sho / fmax(Po, 1.0)) : 0.0;
            out[0] = (float)(0.5 * Lbce + (LhH + LhO));
        }
    }
}

extern "C" void kernel_launch(void* const* d_in, const int* in_sizes, int n_in,
                              void* d_out, int out_size) {
    const float* h  = (const float*)d_in[0];
    const float* o  = (const float*)d_in[1];
    const float* gh = (const float*)d_in[2];
    const float* go = (const float*)d_in[3];

    k_initprep<<<(2*NO + 255)/256, 256>>>(o, go);   // 256 blocks: covers all init ranges
    dim3 gp(RCHUNKS * JCHUNKS, BT, 2);              // 56 x 16 x 2 = 1792 blocks
    k_pair<<<gp, TPB>>>(h, gh);
    dim3 gl(LOSS_BLOCKS, 2);
    k_loss<<<gl, 256>>>((float*)d_out);
}